// round 12
// baseline (speedup 1.0000x reference)
#include <cuda_runtime.h>
#include <cuda_fp16.h>
#include <cstdint>

// Problem constants
#define Bv   8
#define Tv   256
#define Nv   32
#define Dv   4
#define Ev   992
#define Kv   2

#define NEB  8                // edge blocks: 8 x (4 nodes x 32 slots)
#define H1S  72               // h1 row stride in halfs (144B, conflict-free ldsm)

#define NTILES 2048
#define GRID   592            // 148 SMs x 4 CTAs: exactly one resident wave

#define OUT1_ELEMS (8 * 32 * 255 * 4)   // 261120
#define OUT2_ELEMS (8 * 992 * 2)        // 15872

#define SX_OFF   0
#define SAGG_OFF 128
#define SCR_OFF  2176
#define SMEM_FLOATS (2176 + 11776)      // 13952
#define SMEM_BYTES  (SMEM_FLOATS * 4)   // 55808 -> 4 CTAs/SM

typedef unsigned long long u64;

// ---- precomputed weight layouts (written by prep_kernel every launch) ----
__device__ uint32_t g_W2f[2][2][8][32][4];   // [k][mh][chunk][lane][j] mma A-frags
__device__ __half   g_Wo1h[2][80][64];       // [panel][row(80, zero-padded)][col]
__device__ __half   g_Wo2h[2][128][64];      // [panel][row][col]

__device__ __forceinline__ uint32_t smem_u32(const void* p) {
    return (uint32_t)__cvta_generic_to_shared(p);
}
__device__ __forceinline__ void ldsm_x4(uint32_t* r, uint32_t addr) {
    asm volatile("ldmatrix.sync.aligned.m8n8.x4.shared.b16 {%0,%1,%2,%3}, [%4];"
                 : "=r"(r[0]), "=r"(r[1]), "=r"(r[2]), "=r"(r[3]) : "r"(addr));
}
__device__ __forceinline__ void ldsm_x2t(uint32_t& b0, uint32_t& b1, uint32_t addr) {
    asm volatile("ldmatrix.sync.aligned.m8n8.x2.trans.shared.b16 {%0,%1}, [%2];"
                 : "=r"(b0), "=r"(b1) : "r"(addr));
}
__device__ __forceinline__ void ldsm_x2(uint32_t& b0, uint32_t& b1, uint32_t addr) {
    asm volatile("ldmatrix.sync.aligned.m8n8.x2.shared.b16 {%0,%1}, [%2];"
                 : "=r"(b0), "=r"(b1) : "r"(addr));
}
__device__ __forceinline__ void mma16816(float* c, const uint32_t* a,
                                         uint32_t b0, uint32_t b1) {
    asm volatile(
        "mma.sync.aligned.m16n8k16.row.col.f32.f16.f16.f32 "
        "{%0,%1,%2,%3}, {%4,%5,%6,%7}, {%8,%9}, {%0,%1,%2,%3};"
        : "+f"(c[0]), "+f"(c[1]), "+f"(c[2]), "+f"(c[3])
        : "r"(a[0]), "r"(a[1]), "r"(a[2]), "r"(a[3]), "r"(b0), "r"(b1));
}
__device__ __forceinline__ uint32_t h2addrelu(uint32_t a, uint32_t b) {
    __half2 r = __hmax2(__hadd2(*(__half2*)&a, *(__half2*)&b),
                        __float2half2_rn(0.0f));
    return *(uint32_t*)&r;
}
__device__ __forceinline__ uint32_t f2h2(float lo, float hi) {
    __half2 h = __floats2half2_rn(lo, hi);
    return *(uint32_t*)&h;
}

// ---- prep + rel_graph bcast merged into one launch ----
__global__ void prep_kernel(const float* __restrict__ W2,
                            const float* __restrict__ Wo1,
                            const float* __restrict__ Wo2,
                            const float* __restrict__ G,
                            float* __restrict__ out)
{
    int tid = blockIdx.x * 256 + threadIdx.x;

    if (tid < 4096) {   // W2 fragments: [k][mh][c][lane][j]
        int j    = tid & 3;
        int lane = (tid >> 2) & 31;
        int c    = (tid >> 7) & 7;
        int mh   = (tid >> 10) & 1;
        int k    = tid >> 11;
        int mt = c >> 2, ks = c & 3;
        int r_ = lane >> 2, c_ = (lane & 3) * 2;
        int m0 = mh * 32 + mt * 16 + r_;
        int kc = ks * 16 + c_;
        int kk = kc + ((j >= 2) ? 8 : 0);
        int mm = m0 + ((j & 1) ? 8 : 0);
        const float* W2k = W2 + k * 4096;
        g_W2f[k][mh][c][lane][j] = f2h2(W2k[kk * 64 + mm], W2k[(kk + 1) * 64 + mm]);
    }
    if (tid < 10240) {  // Wo1 -> fp16 panels [2][80][64], rows 68..79 zero
        int c = tid & 63;
        int r = (tid >> 6) % 80;
        int p = tid / (80 * 64);
        g_Wo1h[p][r][c] = (r < 68) ? __float2half_rn(Wo1[r * 128 + p * 64 + c])
                                   : __float2half_rn(0.0f);
    }
    if (tid < 16384) {  // Wo2 -> fp16 panels [2][128][64]
        int c = tid & 63;
        int r = (tid >> 6) & 127;
        int p = tid >> 13;
        g_Wo2h[p][r][c] = __float2half_rn(Wo2[r * 128 + p * 64 + c]);
    }
    if (tid < OUT2_ELEMS) {   // rel_graph broadcast into output section 2
        out[OUT1_ELEMS + tid] = G[tid % (Ev * Kv)];
    }
}

extern __shared__ float sm[];

// build h1 rows for edge block eb into given buffer (all 256 threads)
__device__ __forceinline__ void build_h1(__half* buf, const __half* suS,
                                         const __half* suR, int eb, int tid)
{
    int row  = tid >> 1;
    int h0   = (tid & 1) * 32;
    int nl   = row >> 5;
    int slot = row & 31;
    int i    = eb * 4 + nl;
    int jj   = (slot == 31) ? i : (slot + (slot >= i ? 1 : 0));
    const uint4* ps = (const uint4*)(suS + jj * H1S + h0);
    const uint4* pr = (const uint4*)(suR + i * H1S + h0);
    uint4* dst = (uint4*)(buf + row * H1S + h0);
    #pragma unroll
    for (int u = 0; u < 4; ++u) {
        uint4 av = ps[u], cv = pr[u], o;
        o.x = h2addrelu(av.x, cv.x);
        o.y = h2addrelu(av.y, cv.y);
        o.z = h2addrelu(av.z, cv.z);
        o.w = h2addrelu(av.w, cv.w);
        dst[u] = o;
    }
}

__global__ void __launch_bounds__(256, 4)
mlpdec_fused_kernel(const float* __restrict__ X,
                    const float* __restrict__ G,
                    const float* __restrict__ W1,
                    const float* __restrict__ b1,
                    const float* __restrict__ b2,
                    const float* __restrict__ bo1,
                    const float* __restrict__ bo2,
                    const float* __restrict__ Wo3,
                    const float* __restrict__ bo3,
                    float* __restrict__ out)
{
    const int tid = threadIdx.x;
    const int wid  = tid >> 5;
    const int lane = tid & 31;

    float* sx   = sm + SX_OFF;
    float* sagg = sm + SAGG_OFF;
    float* scr  = sm + SCR_OFF;

    __half* suS = (__half*)(scr);
    __half* suR = (__half*)(scr + 1152);
    __half* h1A = (__half*)(scr + 2304);    // 128 x 72 halfs
    __half* h1B = (__half*)(scr + 6912);    // 128 x 72 halfs
    float*  sgA = scr + 11520;              // 128 gates (buffer A)
    float*  sgB = scr + 11648;              // 128 gates (buffer B)
    float*  sWt = scr + 6912;               // aliases h1B (dead at staging time)

    // warp roles in edge GEMM (C = W2^T @ h1^T)
    const int node = wid >> 1;
    const int mh   = wid & 1;
    const int r_ = lane >> 2;
    const int c_ = (lane & 3) * 2;

    // persistent loop over (b,t) tiles: one resident wave, 3-4 tiles per CTA
    for (int bt = blockIdx.x; bt < NTILES; bt += GRID) {
        const int b = bt >> 8;
        const int t = bt & 255;

        __syncthreads();   // previous tile's node phase done with scr/sx

        // ---- load x ----
        if (tid < Nv * Dv) {
            int n = tid >> 2, d = tid & 3;
            sx[tid] = X[(((b * Nv + n) * Tv + t) << 2) + d];
        }

        // ================= edge message passing =================
        for (int k = 0; k < Kv; ++k) {
            __syncthreads();   // prior readers of h1B/suS/suR done
            for (int i = tid; i < 512; i += 256) sWt[i] = W1[k * 512 + i];
            if (tid < 64) sWt[512 + tid] = b1[k * 64 + tid];
            __syncthreads();

            // per-node projections -> fp16
            for (int idx = tid; idx < Nv * 64; idx += 256) {
                int n = idx >> 6, h = idx & 63;
                float x0 = sx[n * 4 + 0], x1 = sx[n * 4 + 1];
                float x2 = sx[n * 4 + 2], x3 = sx[n * 4 + 3];
                float vs = x0 * sWt[0 * 64 + h] + x1 * sWt[1 * 64 + h]
                         + x2 * sWt[2 * 64 + h] + x3 * sWt[3 * 64 + h];
                float vr = sWt[512 + h]
                         + x0 * sWt[4 * 64 + h] + x1 * sWt[5 * 64 + h]
                         + x2 * sWt[6 * 64 + h] + x3 * sWt[7 * 64 + h];
                suS[n * H1S + h] = __float2half_rn(vs);
                suR[n * H1S + h] = __float2half_rn(vr);
            }

            // A-fragments: 8 coalesced LDG.128 from the prepacked layout
            uint32_t a[2][4][4];
            {
                const uint4* src = (const uint4*)&g_W2f[k][mh][0][0][0];
                #pragma unroll
                for (int c = 0; c < 8; ++c) {
                    uint4 v = __ldg(src + c * 32 + lane);
                    a[c >> 2][c & 3][0] = v.x;
                    a[c >> 2][c & 3][1] = v.y;
                    a[c >> 2][c & 3][2] = v.z;
                    a[c >> 2][c & 3][3] = v.w;
                }
            }
            float b2a[2], b2b[2];
            #pragma unroll
            for (int mt = 0; mt < 2; ++mt) {
                b2a[mt] = __ldg(b2 + k * 64 + mh * 32 + mt * 16 + r_);
                b2b[mt] = __ldg(b2 + k * 64 + mh * 32 + mt * 16 + r_ + 8);
            }
            __syncthreads();   // suS/suR ready (h1B alias dead from here)

            // prologue: build block 0 + its gates
            build_h1(h1A, suS, suR, 0, tid);
            if (tid < 128) {
                int slot = tid & 31;
                int i    = tid >> 5;
                sgA[tid] = (slot < 31) ? __ldg(G + (i * 31 + slot) * 2 + k) : 0.0f;
            }

            for (int eb = 0; eb < NEB; ++eb) {
                __syncthreads();   // build(eb)+gates(eb) visible; prev mma drained

                if (eb < NEB - 1) {
                    build_h1((eb & 1) ? h1A : h1B, suS, suR, eb + 1, tid);
                    float* gnext = (eb & 1) ? sgA : sgB;
                    if (tid < 128) {
                        int slot = tid & 31;
                        int i    = (eb + 1) * 4 + (tid >> 5);
                        gnext[tid] = (slot < 31)
                                   ? __ldg(G + (i * 31 + slot) * 2 + k) : 0.0f;
                    }
                }

                const __half* h1c = (eb & 1) ? h1B : h1A;
                const float*  sg  = (eb & 1) ? sgB : sgA;
                const uint32_t bbase = smem_u32(h1c)
                    + ((lane & 7) * H1S + ((lane >> 3) & 1) * 8) * 2;

                float prs[2][2];
                prs[0][0] = prs[0][1] = prs[1][0] = prs[1][1] = 0.0f;

                #pragma unroll
                for (int nt = 0; nt < 4; ++nt) {
                    float acc[2][4];
                    acc[0][0] = acc[0][1] = acc[0][2] = acc[0][3] = 0.0f;
                    acc[1][0] = acc[1][1] = acc[1][2] = acc[1][3] = 0.0f;
                    #pragma unroll
                    for (int ks = 0; ks < 4; ++ks) {
                        uint32_t b0r, b1r;
                        ldsm_x2(b0r, b1r,
                                bbase + ((node * 32 + nt * 8) * H1S + ks * 16) * 2);
                        mma16816(acc[0], a[0][ks], b0r, b1r);
                        mma16816(acc[1], a[1][ks], b0r, b1r);
                    }
                    float2 g2 = *(const float2*)(sg + node * 32 + nt * 8 + c_);
                    #pragma unroll
                    for (int mt = 0; mt < 2; ++mt) {
                        prs[mt][0] += fmaxf(acc[mt][0] + b2a[mt], 0.0f) * g2.x
                                    + fmaxf(acc[mt][1] + b2a[mt], 0.0f) * g2.y;
                        prs[mt][1] += fmaxf(acc[mt][2] + b2b[mt], 0.0f) * g2.x
                                    + fmaxf(acc[mt][3] + b2b[mt], 0.0f) * g2.y;
                    }
                }

                #pragma unroll
                for (int mt = 0; mt < 2; ++mt) {
                    prs[mt][0] += __shfl_xor_sync(0xffffffffu, prs[mt][0], 1);
                    prs[mt][0] += __shfl_xor_sync(0xffffffffu, prs[mt][0], 2);
                    prs[mt][1] += __shfl_xor_sync(0xffffffffu, prs[mt][1], 1);
                    prs[mt][1] += __shfl_xor_sync(0xffffffffu, prs[mt][1], 2);
                }

                if ((lane & 3) == 0) {
                    int n = eb * 4 + node;
                    #pragma unroll
                    for (int mt = 0; mt < 2; ++mt) {
                        int o = n * 64 + mh * 32 + mt * 16 + r_;
                        if (k == 0) {
                            sagg[o]     = prs[mt][0];
                            sagg[o + 8] = prs[mt][1];
                        } else {
                            sagg[o]     += prs[mt][0];
                            sagg[o + 8] += prs[mt][1];
                        }
                    }
                }
            }
        }
        __syncthreads();   // sagg complete before node phase

        // ============ node MLP (tensor cores, 64-col fp16 weight panels) ============
        __half* augH = (__half*)(scr);            // 32 x 88
        __half* p1H  = (__half*)(scr + 1408);     // 32 x 136
        __half* wBH  = (__half*)(scr + 3584);     // 128 x 72
        __half* p2H  = (__half*)(scr + 8192);     // 32 x 136

        const int nmt = wid & 1;                  // m-tile (16 rows)
        const int ng  = wid >> 1;                 // 16-col group within panel

        // build aug fp16 (32 x 80, pad cols 68..79 = 0)
        for (int i = tid; i < 32 * 80; i += 256) {
            int n = i / 80, c = i % 80;
            float v = (c < 4) ? sx[n * 4 + c]
                     : (c < 68 ? sagg[n * 64 + (c - 4)] : 0.0f);
            augH[n * 88 + c] = __float2half_rn(v);
        }
        __syncthreads();

        // ---- layer 1: aug(32x80) @ Wo1(80x128), two prepacked fp16 panels ----
        #pragma unroll
        for (int p = 0; p < 2; ++p) {
            {
                const uint4* wsrc = (const uint4*)&g_Wo1h[p][0][0];  // 640 uint4
                for (int i = tid; i < 640; i += 256) {
                    uint4 v = __ldg(wsrc + i);
                    int r = i >> 3, cc = (i & 7) * 8;
                    *(uint4*)(wBH + r * 72 + cc) = v;
                }
            }
            __syncthreads();

            float acc[2][4];
            acc[0][0] = acc[0][1] = acc[0][2] = acc[0][3] = 0.0f;
            acc[1][0] = acc[1][1] = acc[1][2] = acc[1][3] = 0.0f;
            uint32_t aaddr = smem_u32(augH)
                + ((nmt * 16 + (lane & 15)) * 88 + (lane >> 4) * 8) * 2;
            uint32_t baddr = smem_u32(wBH) + ((lane & 15) * 72) * 2;
            #pragma unroll
            for (int ks = 0; ks < 5; ++ks) {
                uint32_t a[4];
                ldsm_x4(a, aaddr + ks * 32);
                #pragma unroll
                for (int nt = 0; nt < 2; ++nt) {
                    uint32_t b0r, b1r;
                    ldsm_x2t(b0r, b1r,
                             baddr + (ng * 16 + nt * 8) * 2 + ks * 16 * 72 * 2);
                    mma16816(acc[nt], a, b0r, b1r);
                }
            }
            int r = nmt * 16 + r_;
            #pragma unroll
            for (int nt = 0; nt < 2; ++nt) {
                int c  = p * 64 + ng * 16 + nt * 8 + c_;
                float2 bb = __ldg((const float2*)(bo1 + c));
                *(__half2*)(p1H + r * 136 + c) = __floats2half2_rn(
                    fmaxf(acc[nt][0] + bb.x, 0.0f), fmaxf(acc[nt][1] + bb.y, 0.0f));
                *(__half2*)(p1H + (r + 8) * 136 + c) = __floats2half2_rn(
                    fmaxf(acc[nt][2] + bb.x, 0.0f), fmaxf(acc[nt][3] + bb.y, 0.0f));
            }
            __syncthreads();
        }

        // ---- layer 2: p1(32x128) @ Wo2(128x128), two prepacked fp16 panels ----
        #pragma unroll
        for (int p = 0; p < 2; ++p) {
            {
                const uint4* wsrc = (const uint4*)&g_Wo2h[p][0][0];  // 1024 uint4
                for (int i = tid; i < 1024; i += 256) {
                    uint4 v = __ldg(wsrc + i);
                    int r = i >> 3, cc = (i & 7) * 8;
                    *(uint4*)(wBH + r * 72 + cc) = v;
                }
            }
            __syncthreads();

            float acc[2][4];
            acc[0][0] = acc[0][1] = acc[0][2] = acc[0][3] = 0.0f;
            acc[1][0] = acc[1][1] = acc[1][2] = acc[1][3] = 0.0f;
            uint32_t aaddr = smem_u32(p1H)
                + ((nmt * 16 + (lane & 15)) * 136 + (lane >> 4) * 8) * 2;
            uint32_t baddr = smem_u32(wBH) + ((lane & 15) * 72) * 2;
            #pragma unroll
            for (int ks = 0; ks < 8; ++ks) {
                uint32_t a[4];
                ldsm_x4(a, aaddr + ks * 32);
                #pragma unroll
                for (int nt = 0; nt < 2; ++nt) {
                    uint32_t b0r, b1r;
                    ldsm_x2t(b0r, b1r,
                             baddr + (ng * 16 + nt * 8) * 2 + ks * 16 * 72 * 2);
                    mma16816(acc[nt], a, b0r, b1r);
                }
            }
            int r = nmt * 16 + r_;
            #pragma unroll
            for (int nt = 0; nt < 2; ++nt) {
                int c  = p * 64 + ng * 16 + nt * 8 + c_;
                float2 bb = __ldg((const float2*)(bo2 + c));
                *(__half2*)(p2H + r * 136 + c) = __floats2half2_rn(
                    fmaxf(acc[nt][0] + bb.x, 0.0f), fmaxf(acc[nt][1] + bb.y, 0.0f));
                *(__half2*)(p2H + (r + 8) * 136 + c) = __floats2half2_rn(
                    fmaxf(acc[nt][2] + bb.x, 0.0f), fmaxf(acc[nt][3] + bb.y, 0.0f));
            }
            __syncthreads();
        }

        // ---- layer 3 + residual + store ----
        for (int i = tid; i < 512; i += 256) scr[i] = Wo3[i];
        if (tid < 4) scr[512 + tid] = bo3[tid];
        __syncthreads();

        if (tid < 128) {
            int n = tid >> 2, d = tid & 3;
            float s = scr[512 + d] + sx[n * 4 + d];
            const __half2* pr = (const __half2*)(p2H + n * 136);
            #pragma unroll 8
            for (int h2 = 0; h2 < 64; ++h2) {
                float2 v = __half22float2(pr[h2]);
                s += v.x * scr[(2 * h2) * 4 + d] + v.y * scr[(2 * h2 + 1) * 4 + d];
            }
            if (t < Tv - 1)
                out[(((b * Nv + n) * (Tv - 1) + t) << 2) + d] = s;
        }
    }
}

extern "C" void kernel_launch(void* const* d_in, const int* in_sizes, int n_in,
                              void* d_out, int out_size)
{
    const float* X   = (const float*)d_in[0];
    const float* G   = (const float*)d_in[3];
    const float* W1  = (const float*)d_in[4];
    const float* b1  = (const float*)d_in[5];
    const float* W2  = (const float*)d_in[6];
    const float* b2  = (const float*)d_in[7];
    const float* Wo1 = (const float*)d_in[8];
    const float* bo1 = (const float*)d_in[9];
    const float* Wo2 = (const float*)d_in[10];
    const float* bo2 = (const float*)d_in[11];
    const float* Wo3 = (const float*)d_in[12];
    const float* bo3 = (const float*)d_in[13];
    float* out = (float*)d_out;

    cudaFuncSetAttribute(mlpdec_fused_kernel,
                         cudaFuncAttributeMaxDynamicSharedMemorySize, SMEM_BYTES);

    // merged weight repack + rel_graph bcast (single launch before main)
    prep_kernel<<<64, 256>>>(W2, Wo1, Wo2, G, out);

    mlpdec_fused_kernel<<<GRID, 256, SMEM_BYTES>>>(
        X, G, W1, b1, b2, bo1, bo2, Wo3, bo3, out);
}

// round 13
// speedup vs baseline: 1.1137x; 1.1137x over previous
#include <cuda_runtime.h>
#include <cuda_fp16.h>
#include <cstdint>

// Problem constants
#define Bv   8
#define Tv   256
#define Nv   32
#define Dv   4
#define Ev   992
#define Kv   2

#define NEB  8                // edge blocks: 8 x (4 nodes x 32 slots)
#define H1S  72               // h1 row stride in halfs (144B, conflict-free ldsm)

#define OUT1_ELEMS (8 * 32 * 255 * 4)   // 261120
#define OUT2_ELEMS (8 * 992 * 2)        // 15872

#define SX_OFF   0
#define SAGG_OFF 128
#define SCR_OFF  2176
#define SMEM_FLOATS (2176 + 11776)      // 13952
#define SMEM_BYTES  (SMEM_FLOATS * 4)   // 55808 -> 4 CTAs/SM

typedef unsigned long long u64;

// ---- precomputed weight layouts (written by prep_kernel every launch) ----
__device__ uint32_t g_W2f[2][2][8][32][4];   // [k][mh][chunk][lane][j] mma A-frags
__device__ __half   g_Wo1h[2][80][64];       // [panel][row(80, zero-padded)][col]
__device__ __half   g_Wo2h[2][128][64];      // [panel][row][col]

__device__ __forceinline__ uint32_t smem_u32(const void* p) {
    return (uint32_t)__cvta_generic_to_shared(p);
}
__device__ __forceinline__ void ldsm_x4(uint32_t* r, uint32_t addr) {
    asm volatile("ldmatrix.sync.aligned.m8n8.x4.shared.b16 {%0,%1,%2,%3}, [%4];"
                 : "=r"(r[0]), "=r"(r[1]), "=r"(r[2]), "=r"(r[3]) : "r"(addr));
}
__device__ __forceinline__ void ldsm_x2t(uint32_t& b0, uint32_t& b1, uint32_t addr) {
    asm volatile("ldmatrix.sync.aligned.m8n8.x2.trans.shared.b16 {%0,%1}, [%2];"
                 : "=r"(b0), "=r"(b1) : "r"(addr));
}
__device__ __forceinline__ void ldsm_x2(uint32_t& b0, uint32_t& b1, uint32_t addr) {
    asm volatile("ldmatrix.sync.aligned.m8n8.x2.shared.b16 {%0,%1}, [%2];"
                 : "=r"(b0), "=r"(b1) : "r"(addr));
}
__device__ __forceinline__ void mma16816(float* c, const uint32_t* a,
                                         uint32_t b0, uint32_t b1) {
    asm volatile(
        "mma.sync.aligned.m16n8k16.row.col.f32.f16.f16.f32 "
        "{%0,%1,%2,%3}, {%4,%5,%6,%7}, {%8,%9}, {%0,%1,%2,%3};"
        : "+f"(c[0]), "+f"(c[1]), "+f"(c[2]), "+f"(c[3])
        : "r"(a[0]), "r"(a[1]), "r"(a[2]), "r"(a[3]), "r"(b0), "r"(b1));
}
__device__ __forceinline__ uint32_t h2addrelu(uint32_t a, uint32_t b) {
    __half2 r = __hmax2(__hadd2(*(__half2*)&a, *(__half2*)&b),
                        __float2half2_rn(0.0f));
    return *(uint32_t*)&r;
}
__device__ __forceinline__ uint32_t f2h2(float lo, float hi) {
    __half2 h = __floats2half2_rn(lo, hi);
    return *(uint32_t*)&h;
}

// ---- prep + rel_graph bcast merged into one launch ----
__global__ void prep_kernel(const float* __restrict__ W2,
                            const float* __restrict__ Wo1,
                            const float* __restrict__ Wo2,
                            const float* __restrict__ G,
                            float* __restrict__ out)
{
    int tid = blockIdx.x * 256 + threadIdx.x;

    if (tid < 4096) {   // W2 fragments: [k][mh][c][lane][j]
        int j    = tid & 3;
        int lane = (tid >> 2) & 31;
        int c    = (tid >> 7) & 7;
        int mh   = (tid >> 10) & 1;
        int k    = tid >> 11;
        int mt = c >> 2, ks = c & 3;
        int r_ = lane >> 2, c_ = (lane & 3) * 2;
        int m0 = mh * 32 + mt * 16 + r_;
        int kc = ks * 16 + c_;
        int kk = kc + ((j >= 2) ? 8 : 0);
        int mm = m0 + ((j & 1) ? 8 : 0);
        const float* W2k = W2 + k * 4096;
        g_W2f[k][mh][c][lane][j] = f2h2(W2k[kk * 64 + mm], W2k[(kk + 1) * 64 + mm]);
    }
    if (tid < 10240) {  // Wo1 -> fp16 panels [2][80][64], rows 68..79 zero
        int c = tid & 63;
        int r = (tid >> 6) % 80;
        int p = tid / (80 * 64);
        g_Wo1h[p][r][c] = (r < 68) ? __float2half_rn(Wo1[r * 128 + p * 64 + c])
                                   : __float2half_rn(0.0f);
    }
    if (tid < 16384) {  // Wo2 -> fp16 panels [2][128][64]
        int c = tid & 63;
        int r = (tid >> 6) & 127;
        int p = tid >> 13;
        g_Wo2h[p][r][c] = __float2half_rn(Wo2[r * 128 + p * 64 + c]);
    }
    if (tid < OUT2_ELEMS) {   // rel_graph broadcast into output section 2
        out[OUT1_ELEMS + tid] = G[tid % (Ev * Kv)];
    }
}

extern __shared__ float sm[];

// build h1 rows for edge block eb into given buffer (all 256 threads)
__device__ __forceinline__ void build_h1(__half* buf, const __half* suS,
                                         const __half* suR, int eb, int tid)
{
    int row  = tid >> 1;
    int h0   = (tid & 1) * 32;
    int nl   = row >> 5;
    int slot = row & 31;
    int i    = eb * 4 + nl;
    int jj   = (slot == 31) ? i : (slot + (slot >= i ? 1 : 0));
    const uint4* ps = (const uint4*)(suS + jj * H1S + h0);
    const uint4* pr = (const uint4*)(suR + i * H1S + h0);
    uint4* dst = (uint4*)(buf + row * H1S + h0);
    #pragma unroll
    for (int u = 0; u < 4; ++u) {
        uint4 av = ps[u], cv = pr[u], o;
        o.x = h2addrelu(av.x, cv.x);
        o.y = h2addrelu(av.y, cv.y);
        o.z = h2addrelu(av.z, cv.z);
        o.w = h2addrelu(av.w, cv.w);
        dst[u] = o;
    }
}

__global__ void __launch_bounds__(256, 4)
mlpdec_fused_kernel(const float* __restrict__ X,
                    const float* __restrict__ G,
                    const float* __restrict__ W1,
                    const float* __restrict__ b1,
                    const float* __restrict__ b2,
                    const float* __restrict__ bo1,
                    const float* __restrict__ bo2,
                    const float* __restrict__ Wo3,
                    const float* __restrict__ bo3,
                    float* __restrict__ out)
{
    const int bt  = blockIdx.x;
    const int b   = bt >> 8;
    const int t   = bt & 255;
    const int tid = threadIdx.x;
    const int wid  = tid >> 5;
    const int lane = tid & 31;

    float* sx   = sm + SX_OFF;
    float* sagg = sm + SAGG_OFF;
    float* scr  = sm + SCR_OFF;

    __half* suS = (__half*)(scr);
    __half* suR = (__half*)(scr + 1152);
    __half* h1A = (__half*)(scr + 2304);    // 128 x 72 halfs
    __half* h1B = (__half*)(scr + 6912);    // 128 x 72 halfs
    float*  sgA = scr + 11520;              // 128 gates (buffer A)
    float*  sgB = scr + 11648;              // 128 gates (buffer B)

    // ---- load x ----
    if (tid < Nv * Dv) {
        int n = tid >> 2, d = tid & 3;
        sx[tid] = X[(((b * Nv + n) * Tv + t) << 2) + d];
    }
    __syncthreads();

    // warp roles in edge GEMM (C = W2^T @ h1^T)
    const int node = wid >> 1;
    const int mh   = wid & 1;
    const int r_ = lane >> 2;
    const int c_ = (lane & 3) * 2;

    // ================= edge message passing =================
    for (int k = 0; k < Kv; ++k) {
        if (k > 0) __syncthreads();   // k=0 readers of suS/suR/h1 done

        // per-node projections -> fp16 (W1/b1 straight from global, L1-hot)
        {
            const float* W1k = W1 + k * 512;
            const float* b1k = b1 + k * 64;
            for (int idx = tid; idx < Nv * 64; idx += 256) {
                int n = idx >> 6, h = idx & 63;
                float x0 = sx[n * 4 + 0], x1 = sx[n * 4 + 1];
                float x2 = sx[n * 4 + 2], x3 = sx[n * 4 + 3];
                float vs = x0 * __ldg(W1k + h)       + x1 * __ldg(W1k + 64 + h)
                         + x2 * __ldg(W1k + 128 + h) + x3 * __ldg(W1k + 192 + h);
                float vr = __ldg(b1k + h)
                         + x0 * __ldg(W1k + 256 + h) + x1 * __ldg(W1k + 320 + h)
                         + x2 * __ldg(W1k + 384 + h) + x3 * __ldg(W1k + 448 + h);
                suS[n * H1S + h] = __float2half_rn(vs);
                suR[n * H1S + h] = __float2half_rn(vr);
            }
        }

        // A-fragments: 8 coalesced LDG.128 from the prepacked layout
        uint32_t a[2][4][4];
        {
            const uint4* src = (const uint4*)&g_W2f[k][mh][0][0][0];
            #pragma unroll
            for (int c = 0; c < 8; ++c) {
                uint4 v = __ldg(src + c * 32 + lane);
                a[c >> 2][c & 3][0] = v.x;
                a[c >> 2][c & 3][1] = v.y;
                a[c >> 2][c & 3][2] = v.z;
                a[c >> 2][c & 3][3] = v.w;
            }
        }
        float b2a[2], b2b[2];
        #pragma unroll
        for (int mt = 0; mt < 2; ++mt) {
            b2a[mt] = __ldg(b2 + k * 64 + mh * 32 + mt * 16 + r_);
            b2b[mt] = __ldg(b2 + k * 64 + mh * 32 + mt * 16 + r_ + 8);
        }
        __syncthreads();   // suS/suR ready

        // prologue: build block 0 + its gates
        build_h1(h1A, suS, suR, 0, tid);
        if (tid < 128) {
            int slot = tid & 31;
            int i    = tid >> 5;
            sgA[tid] = (slot < 31) ? __ldg(G + (i * 31 + slot) * 2 + k) : 0.0f;
        }

        for (int eb = 0; eb < NEB; ++eb) {
            __syncthreads();   // build(eb)+gates(eb) visible; prev mma drained

            if (eb < NEB - 1) {
                build_h1((eb & 1) ? h1A : h1B, suS, suR, eb + 1, tid);
                float* gnext = (eb & 1) ? sgA : sgB;
                if (tid < 128) {
                    int slot = tid & 31;
                    int i    = (eb + 1) * 4 + (tid >> 5);
                    gnext[tid] = (slot < 31)
                               ? __ldg(G + (i * 31 + slot) * 2 + k) : 0.0f;
                }
            }

            const __half* h1c = (eb & 1) ? h1B : h1A;
            const float*  sg  = (eb & 1) ? sgB : sgA;
            const uint32_t bbase = smem_u32(h1c)
                + ((lane & 7) * H1S + ((lane >> 3) & 1) * 8) * 2;

            float prs[2][2];
            prs[0][0] = prs[0][1] = prs[1][0] = prs[1][1] = 0.0f;

            #pragma unroll
            for (int nt = 0; nt < 4; ++nt) {
                float acc[2][4];
                acc[0][0] = acc[0][1] = acc[0][2] = acc[0][3] = 0.0f;
                acc[1][0] = acc[1][1] = acc[1][2] = acc[1][3] = 0.0f;
                #pragma unroll
                for (int ks = 0; ks < 4; ++ks) {
                    uint32_t b0r, b1r;
                    ldsm_x2(b0r, b1r,
                            bbase + ((node * 32 + nt * 8) * H1S + ks * 16) * 2);
                    mma16816(acc[0], a[0][ks], b0r, b1r);
                    mma16816(acc[1], a[1][ks], b0r, b1r);
                }
                float2 g2 = *(const float2*)(sg + node * 32 + nt * 8 + c_);
                #pragma unroll
                for (int mt = 0; mt < 2; ++mt) {
                    prs[mt][0] += fmaxf(acc[mt][0] + b2a[mt], 0.0f) * g2.x
                                + fmaxf(acc[mt][1] + b2a[mt], 0.0f) * g2.y;
                    prs[mt][1] += fmaxf(acc[mt][2] + b2b[mt], 0.0f) * g2.x
                                + fmaxf(acc[mt][3] + b2b[mt], 0.0f) * g2.y;
                }
            }

            #pragma unroll
            for (int mt = 0; mt < 2; ++mt) {
                prs[mt][0] += __shfl_xor_sync(0xffffffffu, prs[mt][0], 1);
                prs[mt][0] += __shfl_xor_sync(0xffffffffu, prs[mt][0], 2);
                prs[mt][1] += __shfl_xor_sync(0xffffffffu, prs[mt][1], 1);
                prs[mt][1] += __shfl_xor_sync(0xffffffffu, prs[mt][1], 2);
            }

            if ((lane & 3) == 0) {
                int n = eb * 4 + node;
                #pragma unroll
                for (int mt = 0; mt < 2; ++mt) {
                    int o = n * 64 + mh * 32 + mt * 16 + r_;
                    if (k == 0) {
                        sagg[o]     = prs[mt][0];
                        sagg[o + 8] = prs[mt][1];
                    } else {
                        sagg[o]     += prs[mt][0];
                        sagg[o + 8] += prs[mt][1];
                    }
                }
            }
        }
    }
    __syncthreads();   // sagg complete before node phase

    // ================= node MLP (tensor cores, 64-col fp16 weight panels) =================
    __half* augH = (__half*)(scr);            // 32 x 88
    __half* p1H  = (__half*)(scr + 1408);     // 32 x 136
    __half* wBH  = (__half*)(scr + 3584);     // 128 x 72
    __half* p2H  = (__half*)(scr + 8192);     // 32 x 136

    const int nmt = wid & 1;                  // m-tile (16 rows)
    const int ng  = wid >> 1;                 // 16-col group within panel

    // build aug fp16 (32 x 80, pad cols 68..79 = 0)
    for (int i = tid; i < 32 * 80; i += 256) {
        int n = i / 80, c = i % 80;
        float v = (c < 4) ? sx[n * 4 + c]
                 : (c < 68 ? sagg[n * 64 + (c - 4)] : 0.0f);
        augH[n * 88 + c] = __float2half_rn(v);
    }
    __syncthreads();

    // ---- layer 1: aug(32x80) @ Wo1(80x128), two prepacked fp16 panels ----
    #pragma unroll
    for (int p = 0; p < 2; ++p) {
        {
            const uint4* wsrc = (const uint4*)&g_Wo1h[p][0][0];  // 640 uint4
            for (int i = tid; i < 640; i += 256) {
                uint4 v = __ldg(wsrc + i);
                int r = i >> 3, cc = (i & 7) * 8;
                *(uint4*)(wBH + r * 72 + cc) = v;
            }
        }
        __syncthreads();

        float acc[2][4];
        acc[0][0] = acc[0][1] = acc[0][2] = acc[0][3] = 0.0f;
        acc[1][0] = acc[1][1] = acc[1][2] = acc[1][3] = 0.0f;
        uint32_t aaddr = smem_u32(augH)
            + ((nmt * 16 + (lane & 15)) * 88 + (lane >> 4) * 8) * 2;
        uint32_t baddr = smem_u32(wBH) + ((lane & 15) * 72) * 2;
        #pragma unroll
        for (int ks = 0; ks < 5; ++ks) {
            uint32_t a[4];
            ldsm_x4(a, aaddr + ks * 32);
            #pragma unroll
            for (int nt = 0; nt < 2; ++nt) {
                uint32_t b0r, b1r;
                ldsm_x2t(b0r, b1r,
                         baddr + (ng * 16 + nt * 8) * 2 + ks * 16 * 72 * 2);
                mma16816(acc[nt], a, b0r, b1r);
            }
        }
        int r = nmt * 16 + r_;
        #pragma unroll
        for (int nt = 0; nt < 2; ++nt) {
            int c  = p * 64 + ng * 16 + nt * 8 + c_;
            float2 bb = __ldg((const float2*)(bo1 + c));
            *(__half2*)(p1H + r * 136 + c) = __floats2half2_rn(
                fmaxf(acc[nt][0] + bb.x, 0.0f), fmaxf(acc[nt][1] + bb.y, 0.0f));
            *(__half2*)(p1H + (r + 8) * 136 + c) = __floats2half2_rn(
                fmaxf(acc[nt][2] + bb.x, 0.0f), fmaxf(acc[nt][3] + bb.y, 0.0f));
        }
        __syncthreads();
    }

    // ---- layer 2: p1(32x128) @ Wo2(128x128), two prepacked fp16 panels ----
    #pragma unroll
    for (int p = 0; p < 2; ++p) {
        {
            const uint4* wsrc = (const uint4*)&g_Wo2h[p][0][0];  // 1024 uint4
            for (int i = tid; i < 1024; i += 256) {
                uint4 v = __ldg(wsrc + i);
                int r = i >> 3, cc = (i & 7) * 8;
                *(uint4*)(wBH + r * 72 + cc) = v;
            }
        }
        __syncthreads();

        float acc[2][4];
        acc[0][0] = acc[0][1] = acc[0][2] = acc[0][3] = 0.0f;
        acc[1][0] = acc[1][1] = acc[1][2] = acc[1][3] = 0.0f;
        uint32_t aaddr = smem_u32(p1H)
            + ((nmt * 16 + (lane & 15)) * 136 + (lane >> 4) * 8) * 2;
        uint32_t baddr = smem_u32(wBH) + ((lane & 15) * 72) * 2;
        #pragma unroll
        for (int ks = 0; ks < 8; ++ks) {
            uint32_t a[4];
            ldsm_x4(a, aaddr + ks * 32);
            #pragma unroll
            for (int nt = 0; nt < 2; ++nt) {
                uint32_t b0r, b1r;
                ldsm_x2t(b0r, b1r,
                         baddr + (ng * 16 + nt * 8) * 2 + ks * 16 * 72 * 2);
                mma16816(acc[nt], a, b0r, b1r);
            }
        }
        int r = nmt * 16 + r_;
        #pragma unroll
        for (int nt = 0; nt < 2; ++nt) {
            int c  = p * 64 + ng * 16 + nt * 8 + c_;
            float2 bb = __ldg((const float2*)(bo2 + c));
            *(__half2*)(p2H + r * 136 + c) = __floats2half2_rn(
                fmaxf(acc[nt][0] + bb.x, 0.0f), fmaxf(acc[nt][1] + bb.y, 0.0f));
            *(__half2*)(p2H + (r + 8) * 136 + c) = __floats2half2_rn(
                fmaxf(acc[nt][2] + bb.x, 0.0f), fmaxf(acc[nt][3] + bb.y, 0.0f));
        }
        __syncthreads();
    }

    // ---- layer 3 + residual + store ----
    for (int i = tid; i < 512; i += 256) scr[i] = Wo3[i];
    if (tid < 4) scr[512 + tid] = bo3[tid];
    __syncthreads();

    if (tid < 128) {
        int n = tid >> 2, d = tid & 3;
        float s = scr[512 + d] + sx[n * 4 + d];
        const __half2* pr = (const __half2*)(p2H + n * 136);
        #pragma unroll 8
        for (int h2 = 0; h2 < 64; ++h2) {
            float2 v = __half22float2(pr[h2]);
            s += v.x * scr[(2 * h2) * 4 + d] + v.y * scr[(2 * h2 + 1) * 4 + d];
        }
        if (t < Tv - 1)
            out[(((b * Nv + n) * (Tv - 1) + t) << 2) + d] = s;
    }
}

extern "C" void kernel_launch(void* const* d_in, const int* in_sizes, int n_in,
                              void* d_out, int out_size)
{
    const float* X   = (const float*)d_in[0];
    const float* G   = (const float*)d_in[3];
    const float* W1  = (const float*)d_in[4];
    const float* b1  = (const float*)d_in[5];
    const float* W2  = (const float*)d_in[6];
    const float* b2  = (const float*)d_in[7];
    const float* Wo1 = (const float*)d_in[8];
    const float* bo1 = (const float*)d_in[9];
    const float* Wo2 = (const float*)d_in[10];
    const float* bo2 = (const float*)d_in[11];
    const float* Wo3 = (const float*)d_in[12];
    const float* bo3 = (const float*)d_in[13];
    float* out = (float*)d_out;

    cudaFuncSetAttribute(mlpdec_fused_kernel,
                         cudaFuncAttributeMaxDynamicSharedMemorySize, SMEM_BYTES);

    // merged weight repack + rel_graph bcast (single launch before main)
    prep_kernel<<<64, 256>>>(W2, Wo1, Wo2, G, out);

    // non-persistent grid: HW CTA scheduler load-balances better than static
    mlpdec_fused_kernel<<<Bv * Tv, 256, SMEM_BYTES>>>(
        X, G, W1, b1, b2, bo1, bo2, Wo3, bo3, out);
}

// round 14
// speedup vs baseline: 1.1577x; 1.0395x over previous
#include <cuda_runtime.h>
#include <cuda_fp16.h>
#include <cstdint>

// Problem constants
#define Bv   8
#define Tv   256
#define Nv   32
#define Dv   4
#define Ev   992
#define Kv   2

#define NEB  8                // edge blocks: 8 x (4 nodes x 32 slots)
#define H1S  72               // h1 row stride in halfs (144B, conflict-free ldsm)

#define OUT1_ELEMS (8 * 32 * 255 * 4)   // 261120
#define OUT2_ELEMS (8 * 992 * 2)        // 15872

#define SX_OFF   0
#define SAGG_OFF 128
#define SCR_OFF  2176
#define SMEM_FLOATS (2176 + 11776)      // 13952
#define SMEM_BYTES  (SMEM_FLOATS * 4)   // 55808 -> 4 CTAs/SM

typedef unsigned long long u64;

// ---- precomputed weight layouts (written by prep_kernel every launch) ----
__device__ uint32_t g_W2f[2][2][8][32][4];   // [k][mh][chunk][lane][j] mma A-frags
__device__ uint4    g_Wo1f[2][5][4][32];     // [panel][ks][ng][lane] B-frags
__device__ uint4    g_Wo2f[2][8][4][32];     // [panel][ks][ng][lane] B-frags

__device__ __forceinline__ uint32_t smem_u32(const void* p) {
    return (uint32_t)__cvta_generic_to_shared(p);
}
__device__ __forceinline__ void ldsm_x4(uint32_t* r, uint32_t addr) {
    asm volatile("ldmatrix.sync.aligned.m8n8.x4.shared.b16 {%0,%1,%2,%3}, [%4];"
                 : "=r"(r[0]), "=r"(r[1]), "=r"(r[2]), "=r"(r[3]) : "r"(addr));
}
__device__ __forceinline__ void ldsm_x2(uint32_t& b0, uint32_t& b1, uint32_t addr) {
    asm volatile("ldmatrix.sync.aligned.m8n8.x2.shared.b16 {%0,%1}, [%2];"
                 : "=r"(b0), "=r"(b1) : "r"(addr));
}
__device__ __forceinline__ void mma16816(float* c, const uint32_t* a,
                                         uint32_t b0, uint32_t b1) {
    asm volatile(
        "mma.sync.aligned.m16n8k16.row.col.f32.f16.f16.f32 "
        "{%0,%1,%2,%3}, {%4,%5,%6,%7}, {%8,%9}, {%0,%1,%2,%3};"
        : "+f"(c[0]), "+f"(c[1]), "+f"(c[2]), "+f"(c[3])
        : "r"(a[0]), "r"(a[1]), "r"(a[2]), "r"(a[3]), "r"(b0), "r"(b1));
}
__device__ __forceinline__ uint32_t h2addrelu(uint32_t a, uint32_t b) {
    __half2 r = __hmax2(__hadd2(*(__half2*)&a, *(__half2*)&b),
                        __float2half2_rn(0.0f));
    return *(uint32_t*)&r;
}
__device__ __forceinline__ uint32_t f2h2(float lo, float hi) {
    __half2 h = __floats2half2_rn(lo, hi);
    return *(uint32_t*)&h;
}

// ---- prep: pack all loop-invariant weights into mma fragment layouts ----
__global__ void prep_kernel(const float* __restrict__ W2,
                            const float* __restrict__ Wo1,
                            const float* __restrict__ Wo2,
                            const float* __restrict__ G,
                            float* __restrict__ out)
{
    int tid = blockIdx.x * 256 + threadIdx.x;

    if (tid < 4096) {   // W2 A-fragments: [k][mh][c][lane][j]
        int j    = tid & 3;
        int lane = (tid >> 2) & 31;
        int c    = (tid >> 7) & 7;
        int mh   = (tid >> 10) & 1;
        int k    = tid >> 11;
        int mt = c >> 2, ks = c & 3;
        int r_ = lane >> 2, c_ = (lane & 3) * 2;
        int m0 = mh * 32 + mt * 16 + r_;
        int kc = ks * 16 + c_;
        int kk = kc + ((j >= 2) ? 8 : 0);
        int mm = m0 + ((j & 1) ? 8 : 0);
        const float* W2k = W2 + k * 4096;
        g_W2f[k][mh][c][lane][j] = f2h2(W2k[kk * 64 + mm], W2k[(kk + 1) * 64 + mm]);
    }
    if (tid < 1280) {   // Wo1 B-fragments [2][5][4][32]; rows >= 68 are zero
        int lane = tid & 31;
        int ng   = (tid >> 5) & 3;
        int ks   = (tid >> 7) % 5;
        int p    = tid / 640;
        int n0 = p * 64 + ng * 16 + (lane >> 2);
        int k0 = ks * 16 + (lane & 3) * 2;
        uint4 v;
        #define WO1P(kk, nn) f2h2(((kk) < 68 ? Wo1[(kk) * 128 + (nn)] : 0.0f), \
                                  (((kk) + 1) < 68 ? Wo1[((kk) + 1) * 128 + (nn)] : 0.0f))
        v.x = WO1P(k0,     n0);
        v.y = WO1P(k0 + 8, n0);
        v.z = WO1P(k0,     n0 + 8);
        v.w = WO1P(k0 + 8, n0 + 8);
        #undef WO1P
        g_Wo1f[p][ks][ng][lane] = v;
    }
    if (tid < 2048) {   // Wo2 B-fragments [2][8][4][32]
        int lane = tid & 31;
        int ng   = (tid >> 5) & 3;
        int ks   = (tid >> 7) & 7;
        int p    = tid >> 10;
        int n0 = p * 64 + ng * 16 + (lane >> 2);
        int k0 = ks * 16 + (lane & 3) * 2;
        uint4 v;
        v.x = f2h2(Wo2[k0 * 128 + n0],       Wo2[(k0 + 1) * 128 + n0]);
        v.y = f2h2(Wo2[(k0 + 8) * 128 + n0], Wo2[(k0 + 9) * 128 + n0]);
        v.z = f2h2(Wo2[k0 * 128 + n0 + 8],       Wo2[(k0 + 1) * 128 + n0 + 8]);
        v.w = f2h2(Wo2[(k0 + 8) * 128 + n0 + 8], Wo2[(k0 + 9) * 128 + n0 + 8]);
        g_Wo2f[p][ks][ng][lane] = v;
    }
    if (tid < OUT2_ELEMS) {   // rel_graph broadcast into output section 2
        out[OUT1_ELEMS + tid] = G[tid % (Ev * Kv)];
    }
}

extern __shared__ float sm[];

// build h1 rows for edge block eb into given buffer (all 256 threads)
__device__ __forceinline__ void build_h1(__half* buf, const __half* suS,
                                         const __half* suR, int eb, int tid)
{
    int row  = tid >> 1;
    int h0   = (tid & 1) * 32;
    int nl   = row >> 5;
    int slot = row & 31;
    int i    = eb * 4 + nl;
    int jj   = (slot == 31) ? i : (slot + (slot >= i ? 1 : 0));
    const uint4* ps = (const uint4*)(suS + jj * H1S + h0);
    const uint4* pr = (const uint4*)(suR + i * H1S + h0);
    uint4* dst = (uint4*)(buf + row * H1S + h0);
    #pragma unroll
    for (int u = 0; u < 4; ++u) {
        uint4 av = ps[u], cv = pr[u], o;
        o.x = h2addrelu(av.x, cv.x);
        o.y = h2addrelu(av.y, cv.y);
        o.z = h2addrelu(av.z, cv.z);
        o.w = h2addrelu(av.w, cv.w);
        dst[u] = o;
    }
}

__global__ void __launch_bounds__(256, 4)
mlpdec_fused_kernel(const float* __restrict__ X,
                    const float* __restrict__ G,
                    const float* __restrict__ W1,
                    const float* __restrict__ b1,
                    const float* __restrict__ b2,
                    const float* __restrict__ bo1,
                    const float* __restrict__ bo2,
                    const float* __restrict__ Wo3,
                    const float* __restrict__ bo3,
                    float* __restrict__ out)
{
    const int bt  = blockIdx.x;
    const int b   = bt >> 8;
    const int t   = bt & 255;
    const int tid = threadIdx.x;
    const int wid  = tid >> 5;
    const int lane = tid & 31;

    float* sx   = sm + SX_OFF;
    float* sagg = sm + SAGG_OFF;
    float* scr  = sm + SCR_OFF;

    __half* suS = (__half*)(scr);
    __half* suR = (__half*)(scr + 1152);
    __half* h1A = (__half*)(scr + 2304);    // 128 x 72 halfs
    __half* h1B = (__half*)(scr + 6912);    // 128 x 72 halfs
    float*  sgA = scr + 11520;              // 128 gates (buffer A)
    float*  sgB = scr + 11648;              // 128 gates (buffer B)

    // ---- load x ----
    if (tid < Nv * Dv) {
        int n = tid >> 2, d = tid & 3;
        sx[tid] = X[(((b * Nv + n) * Tv + t) << 2) + d];
    }
    __syncthreads();

    // warp roles in edge GEMM (C = W2^T @ h1^T)
    const int node = wid >> 1;
    const int mh   = wid & 1;
    const int r_ = lane >> 2;
    const int c_ = (lane & 3) * 2;

    // ================= edge message passing =================
    for (int k = 0; k < Kv; ++k) {
        if (k > 0) __syncthreads();   // k=0 readers of suS/suR/h1 done

        // per-node projections -> fp16 (W1/b1 straight from global, L1-hot)
        {
            const float* W1k = W1 + k * 512;
            const float* b1k = b1 + k * 64;
            for (int idx = tid; idx < Nv * 64; idx += 256) {
                int n = idx >> 6, h = idx & 63;
                float x0 = sx[n * 4 + 0], x1 = sx[n * 4 + 1];
                float x2 = sx[n * 4 + 2], x3 = sx[n * 4 + 3];
                float vs = x0 * __ldg(W1k + h)       + x1 * __ldg(W1k + 64 + h)
                         + x2 * __ldg(W1k + 128 + h) + x3 * __ldg(W1k + 192 + h);
                float vr = __ldg(b1k + h)
                         + x0 * __ldg(W1k + 256 + h) + x1 * __ldg(W1k + 320 + h)
                         + x2 * __ldg(W1k + 384 + h) + x3 * __ldg(W1k + 448 + h);
                suS[n * H1S + h] = __float2half_rn(vs);
                suR[n * H1S + h] = __float2half_rn(vr);
            }
        }

        // A-fragments: 8 coalesced LDG.128 from the prepacked layout
        uint32_t a[2][4][4];
        {
            const uint4* src = (const uint4*)&g_W2f[k][mh][0][0][0];
            #pragma unroll
            for (int c = 0; c < 8; ++c) {
                uint4 v = __ldg(src + c * 32 + lane);
                a[c >> 2][c & 3][0] = v.x;
                a[c >> 2][c & 3][1] = v.y;
                a[c >> 2][c & 3][2] = v.z;
                a[c >> 2][c & 3][3] = v.w;
            }
        }
        float b2a[2], b2b[2];
        #pragma unroll
        for (int mt = 0; mt < 2; ++mt) {
            b2a[mt] = __ldg(b2 + k * 64 + mh * 32 + mt * 16 + r_);
            b2b[mt] = __ldg(b2 + k * 64 + mh * 32 + mt * 16 + r_ + 8);
        }
        __syncthreads();   // suS/suR ready

        // prologue: build block 0 + its gates
        build_h1(h1A, suS, suR, 0, tid);
        if (tid < 128) {
            int slot = tid & 31;
            int i    = tid >> 5;
            sgA[tid] = (slot < 31) ? __ldg(G + (i * 31 + slot) * 2 + k) : 0.0f;
        }

        for (int eb = 0; eb < NEB; ++eb) {
            __syncthreads();   // build(eb)+gates(eb) visible; prev mma drained

            if (eb < NEB - 1) {
                build_h1((eb & 1) ? h1A : h1B, suS, suR, eb + 1, tid);
                float* gnext = (eb & 1) ? sgA : sgB;
                if (tid < 128) {
                    int slot = tid & 31;
                    int i    = (eb + 1) * 4 + (tid >> 5);
                    gnext[tid] = (slot < 31)
                               ? __ldg(G + (i * 31 + slot) * 2 + k) : 0.0f;
                }
            }

            const __half* h1c = (eb & 1) ? h1B : h1A;
            const float*  sg  = (eb & 1) ? sgB : sgA;
            const uint32_t bbase = smem_u32(h1c)
                + ((lane & 7) * H1S + ((lane >> 3) & 1) * 8) * 2;

            float prs[2][2];
            prs[0][0] = prs[0][1] = prs[1][0] = prs[1][1] = 0.0f;

            #pragma unroll
            for (int nt = 0; nt < 4; ++nt) {
                float acc[2][4];
                acc[0][0] = acc[0][1] = acc[0][2] = acc[0][3] = 0.0f;
                acc[1][0] = acc[1][1] = acc[1][2] = acc[1][3] = 0.0f;
                #pragma unroll
                for (int ks = 0; ks < 4; ++ks) {
                    uint32_t b0r, b1r;
                    ldsm_x2(b0r, b1r,
                            bbase + ((node * 32 + nt * 8) * H1S + ks * 16) * 2);
                    mma16816(acc[0], a[0][ks], b0r, b1r);
                    mma16816(acc[1], a[1][ks], b0r, b1r);
                }
                float2 g2 = *(const float2*)(sg + node * 32 + nt * 8 + c_);
                #pragma unroll
                for (int mt = 0; mt < 2; ++mt) {
                    prs[mt][0] += fmaxf(acc[mt][0] + b2a[mt], 0.0f) * g2.x
                                + fmaxf(acc[mt][1] + b2a[mt], 0.0f) * g2.y;
                    prs[mt][1] += fmaxf(acc[mt][2] + b2b[mt], 0.0f) * g2.x
                                + fmaxf(acc[mt][3] + b2b[mt], 0.0f) * g2.y;
                }
            }

            #pragma unroll
            for (int mt = 0; mt < 2; ++mt) {
                prs[mt][0] += __shfl_xor_sync(0xffffffffu, prs[mt][0], 1);
                prs[mt][0] += __shfl_xor_sync(0xffffffffu, prs[mt][0], 2);
                prs[mt][1] += __shfl_xor_sync(0xffffffffu, prs[mt][1], 1);
                prs[mt][1] += __shfl_xor_sync(0xffffffffu, prs[mt][1], 2);
            }

            if ((lane & 3) == 0) {
                int n = eb * 4 + node;
                #pragma unroll
                for (int mt = 0; mt < 2; ++mt) {
                    int o = n * 64 + mh * 32 + mt * 16 + r_;
                    if (k == 0) {
                        sagg[o]     = prs[mt][0];
                        sagg[o + 8] = prs[mt][1];
                    } else {
                        sagg[o]     += prs[mt][0];
                        sagg[o + 8] += prs[mt][1];
                    }
                }
            }
        }
    }
    __syncthreads();   // sagg complete before node phase

    // ====== node MLP (tensor cores, B-fragments direct from global) ======
    __half* augH = (__half*)(scr);            // 32 x 88
    __half* p1H  = (__half*)(scr + 1408);     // 32 x 136
    __half* p2H  = (__half*)(scr + 8192);     // 32 x 136

    const int nmt = wid & 1;                  // m-tile (16 rows)
    const int ng  = wid >> 1;                 // 16-col group within panel

    // build aug fp16 (32 x 80, pad cols 68..79 = 0)
    for (int i = tid; i < 32 * 80; i += 256) {
        int n = i / 80, c = i % 80;
        float v = (c < 4) ? sx[n * 4 + c]
                 : (c < 68 ? sagg[n * 64 + (c - 4)] : 0.0f);
        augH[n * 88 + c] = __float2half_rn(v);
    }
    __syncthreads();

    // ---- layer 1: aug(32x80) @ Wo1(80x128); A-ldsm shared across panels ----
    {
        float acc[2][2][4];    // [panel][nt][4]
        #pragma unroll
        for (int p = 0; p < 2; ++p)
            #pragma unroll
            for (int nt = 0; nt < 2; ++nt)
                acc[p][nt][0] = acc[p][nt][1] = acc[p][nt][2] = acc[p][nt][3] = 0.0f;

        uint32_t aaddr = smem_u32(augH)
            + ((nmt * 16 + (lane & 15)) * 88 + (lane >> 4) * 8) * 2;
        #pragma unroll
        for (int ks = 0; ks < 5; ++ks) {
            uint32_t a[4];
            ldsm_x4(a, aaddr + ks * 32);
            #pragma unroll
            for (int p = 0; p < 2; ++p) {
                uint4 bf = __ldg(&g_Wo1f[p][ks][ng][lane]);
                mma16816(acc[p][0], a, bf.x, bf.y);
                mma16816(acc[p][1], a, bf.z, bf.w);
            }
        }
        int r = nmt * 16 + r_;
        #pragma unroll
        for (int p = 0; p < 2; ++p)
            #pragma unroll
            for (int nt = 0; nt < 2; ++nt) {
                int c  = p * 64 + ng * 16 + nt * 8 + c_;
                float2 bb = __ldg((const float2*)(bo1 + c));
                *(__half2*)(p1H + r * 136 + c) = __floats2half2_rn(
                    fmaxf(acc[p][nt][0] + bb.x, 0.0f),
                    fmaxf(acc[p][nt][1] + bb.y, 0.0f));
                *(__half2*)(p1H + (r + 8) * 136 + c) = __floats2half2_rn(
                    fmaxf(acc[p][nt][2] + bb.x, 0.0f),
                    fmaxf(acc[p][nt][3] + bb.y, 0.0f));
            }
    }
    __syncthreads();

    // ---- layer 2: p1(32x128) @ Wo2(128x128) ----
    {
        float acc[2][2][4];
        #pragma unroll
        for (int p = 0; p < 2; ++p)
            #pragma unroll
            for (int nt = 0; nt < 2; ++nt)
                acc[p][nt][0] = acc[p][nt][1] = acc[p][nt][2] = acc[p][nt][3] = 0.0f;

        uint32_t aaddr = smem_u32(p1H)
            + ((nmt * 16 + (lane & 15)) * 136 + (lane >> 4) * 8) * 2;
        #pragma unroll
        for (int ks = 0; ks < 8; ++ks) {
            uint32_t a[4];
            ldsm_x4(a, aaddr + ks * 32);
            #pragma unroll
            for (int p = 0; p < 2; ++p) {
                uint4 bf = __ldg(&g_Wo2f[p][ks][ng][lane]);
                mma16816(acc[p][0], a, bf.x, bf.y);
                mma16816(acc[p][1], a, bf.z, bf.w);
            }
        }
        int r = nmt * 16 + r_;
        #pragma unroll
        for (int p = 0; p < 2; ++p)
            #pragma unroll
            for (int nt = 0; nt < 2; ++nt) {
                int c  = p * 64 + ng * 16 + nt * 8 + c_;
                float2 bb = __ldg((const float2*)(bo2 + c));
                *(__half2*)(p2H + r * 136 + c) = __floats2half2_rn(
                    fmaxf(acc[p][nt][0] + bb.x, 0.0f),
                    fmaxf(acc[p][nt][1] + bb.y, 0.0f));
                *(__half2*)(p2H + (r + 8) * 136 + c) = __floats2half2_rn(
                    fmaxf(acc[p][nt][2] + bb.x, 0.0f),
                    fmaxf(acc[p][nt][3] + bb.y, 0.0f));
            }
    }
    __syncthreads();

    // ---- layer 3 + residual + store ----
    for (int i = tid; i < 512; i += 256) scr[i] = Wo3[i];
    if (tid < 4) scr[512 + tid] = bo3[tid];
    __syncthreads();

    if (tid < 128) {
        int n = tid >> 2, d = tid & 3;
        float s = scr[512 + d] + sx[n * 4 + d];
        const __half2* pr = (const __half2*)(p2H + n * 136);
        #pragma unroll 8
        for (int h2 = 0; h2 < 64; ++h2) {
            float2 v = __half22float2(pr[h2]);
            s += v.x * scr[(2 * h2) * 4 + d] + v.y * scr[(2 * h2 + 1) * 4 + d];
        }
        if (t < Tv - 1)
            out[(((b * Nv + n) * (Tv - 1) + t) << 2) + d] = s;
    }
}

extern "C" void kernel_launch(void* const* d_in, const int* in_sizes, int n_in,
                              void* d_out, int out_size)
{
    const float* X   = (const float*)d_in[0];
    const float* G   = (const float*)d_in[3];
    const float* W1  = (const float*)d_in[4];
    const float* b1  = (const float*)d_in[5];
    const float* W2  = (const float*)d_in[6];
    const float* b2  = (const float*)d_in[7];
    const float* Wo1 = (const float*)d_in[8];
    const float* bo1 = (const float*)d_in[9];
    const float* Wo2 = (const float*)d_in[10];
    const float* bo2 = (const float*)d_in[11];
    const float* Wo3 = (const float*)d_in[12];
    const float* bo3 = (const float*)d_in[13];
    float* out = (float*)d_out;

    cudaFuncSetAttribute(mlpdec_fused_kernel,
                         cudaFuncAttributeMaxDynamicSharedMemorySize, SMEM_BYTES);

    // merged weight repack + rel_graph bcast (single launch before main)
    prep_kernel<<<64, 256>>>(W2, Wo1, Wo2, G, out);

    mlpdec_fused_kernel<<<Bv * Tv, 256, SMEM_BYTES>>>(
        X, G, W1, b1, b2, bo1, bo2, Wo3, bo3, out);
}

// round 15
// speedup vs baseline: 1.2015x; 1.0378x over previous
#include <cuda_runtime.h>
#include <cuda_fp16.h>
#include <cstdint>

// Problem constants
#define Bv   8
#define Tv   256
#define Nv   32
#define Dv   4
#define Ev   992
#define Kv   2

#define NEB  8                // edge blocks: 8 x (4 nodes x 32 slots)
#define H1S  72               // h1 row stride in halfs (144B, conflict-free ldsm)

#define OUT1_ELEMS (8 * 32 * 255 * 4)   // 261120
#define OUT2_ELEMS (8 * 992 * 2)        // 15872

#define SX_OFF   0
#define SAGG_OFF 128
#define SCR_OFF  2176
#define SMEM_FLOATS (2176 + 11776)      // 13952
#define SMEM_BYTES  (SMEM_FLOATS * 4)   // 55808 -> 4 CTAs/SM

typedef unsigned long long u64;

// ---- precomputed weight layouts (written by prep_kernel every launch) ----
__device__ uint32_t g_W2f[2][2][8][32][4];   // [k][mh][chunk][lane][j] mma A-frags
__device__ uint4    g_Wo1f[2][5][4][32];     // [panel][ks][ng][lane] B-frags
__device__ uint4    g_Wo2f[2][8][4][32];     // [panel][ks][ng][lane] B-frags
__device__ uint2    g_Wo3f[8][32];           // [ks][lane] B-frags (4 cols pad to 8)

__device__ __forceinline__ uint32_t smem_u32(const void* p) {
    return (uint32_t)__cvta_generic_to_shared(p);
}
__device__ __forceinline__ void ldsm_x4(uint32_t* r, uint32_t addr) {
    asm volatile("ldmatrix.sync.aligned.m8n8.x4.shared.b16 {%0,%1,%2,%3}, [%4];"
                 : "=r"(r[0]), "=r"(r[1]), "=r"(r[2]), "=r"(r[3]) : "r"(addr));
}
__device__ __forceinline__ void ldsm_x2(uint32_t& b0, uint32_t& b1, uint32_t addr) {
    asm volatile("ldmatrix.sync.aligned.m8n8.x2.shared.b16 {%0,%1}, [%2];"
                 : "=r"(b0), "=r"(b1) : "r"(addr));
}
__device__ __forceinline__ void mma16816(float* c, const uint32_t* a,
                                         uint32_t b0, uint32_t b1) {
    asm volatile(
        "mma.sync.aligned.m16n8k16.row.col.f32.f16.f16.f32 "
        "{%0,%1,%2,%3}, {%4,%5,%6,%7}, {%8,%9}, {%0,%1,%2,%3};"
        : "+f"(c[0]), "+f"(c[1]), "+f"(c[2]), "+f"(c[3])
        : "r"(a[0]), "r"(a[1]), "r"(a[2]), "r"(a[3]), "r"(b0), "r"(b1));
}
__device__ __forceinline__ uint32_t h2addrelu(uint32_t a, uint32_t b) {
    __half2 r = __hmax2(__hadd2(*(__half2*)&a, *(__half2*)&b),
                        __float2half2_rn(0.0f));
    return *(uint32_t*)&r;
}
__device__ __forceinline__ uint32_t f2h2(float lo, float hi) {
    __half2 h = __floats2half2_rn(lo, hi);
    return *(uint32_t*)&h;
}

// ---- prep: pack all loop-invariant weights into mma fragment layouts ----
__global__ void prep_kernel(const float* __restrict__ W2,
                            const float* __restrict__ Wo1,
                            const float* __restrict__ Wo2,
                            const float* __restrict__ Wo3,
                            const float* __restrict__ G,
                            float* __restrict__ out)
{
    int tid = blockIdx.x * 256 + threadIdx.x;

    if (tid < 4096) {   // W2 A-fragments: [k][mh][c][lane][j]
        int j    = tid & 3;
        int lane = (tid >> 2) & 31;
        int c    = (tid >> 7) & 7;
        int mh   = (tid >> 10) & 1;
        int k    = tid >> 11;
        int mt = c >> 2, ks = c & 3;
        int r_ = lane >> 2, c_ = (lane & 3) * 2;
        int m0 = mh * 32 + mt * 16 + r_;
        int kc = ks * 16 + c_;
        int kk = kc + ((j >= 2) ? 8 : 0);
        int mm = m0 + ((j & 1) ? 8 : 0);
        const float* W2k = W2 + k * 4096;
        g_W2f[k][mh][c][lane][j] = f2h2(W2k[kk * 64 + mm], W2k[(kk + 1) * 64 + mm]);
    }
    if (tid < 1280) {   // Wo1 B-fragments [2][5][4][32]; rows >= 68 are zero
        int lane = tid & 31;
        int ng   = (tid >> 5) & 3;
        int ks   = (tid >> 7) % 5;
        int p    = tid / 640;
        int n0 = p * 64 + ng * 16 + (lane >> 2);
        int k0 = ks * 16 + (lane & 3) * 2;
        uint4 v;
        #define WO1P(kk, nn) f2h2(((kk) < 68 ? Wo1[(kk) * 128 + (nn)] : 0.0f), \
                                  (((kk) + 1) < 68 ? Wo1[((kk) + 1) * 128 + (nn)] : 0.0f))
        v.x = WO1P(k0,     n0);
        v.y = WO1P(k0 + 8, n0);
        v.z = WO1P(k0,     n0 + 8);
        v.w = WO1P(k0 + 8, n0 + 8);
        #undef WO1P
        g_Wo1f[p][ks][ng][lane] = v;
    }
    if (tid < 2048) {   // Wo2 B-fragments [2][8][4][32]
        int lane = tid & 31;
        int ng   = (tid >> 5) & 3;
        int ks   = (tid >> 7) & 7;
        int p    = tid >> 10;
        int n0 = p * 64 + ng * 16 + (lane >> 2);
        int k0 = ks * 16 + (lane & 3) * 2;
        uint4 v;
        v.x = f2h2(Wo2[k0 * 128 + n0],       Wo2[(k0 + 1) * 128 + n0]);
        v.y = f2h2(Wo2[(k0 + 8) * 128 + n0], Wo2[(k0 + 9) * 128 + n0]);
        v.z = f2h2(Wo2[k0 * 128 + n0 + 8],       Wo2[(k0 + 1) * 128 + n0 + 8]);
        v.w = f2h2(Wo2[(k0 + 8) * 128 + n0 + 8], Wo2[(k0 + 9) * 128 + n0 + 8]);
        g_Wo2f[p][ks][ng][lane] = v;
    }
    if (tid < 256) {    // Wo3 B-fragments [8][32]; cols >= 4 are zero
        int lane = tid & 31;
        int ks   = tid >> 5;
        int n  = lane >> 2;                  // 0..7 (valid 0..3)
        int k0 = ks * 16 + (lane & 3) * 2;
        uint2 v;
        #define WO3P(kk) f2h2((n < 4 ? Wo3[(kk) * 4 + n] : 0.0f), \
                              (n < 4 ? Wo3[((kk) + 1) * 4 + n] : 0.0f))
        v.x = WO3P(k0);
        v.y = WO3P(k0 + 8);
        #undef WO3P
        g_Wo3f[ks][lane] = v;
    }
    if (tid < OUT2_ELEMS) {   // rel_graph broadcast into output section 2
        out[OUT1_ELEMS + tid] = G[tid % (Ev * Kv)];
    }
}

extern __shared__ float sm[];

// build h1 rows for edge block eb into given buffer (all 256 threads)
__device__ __forceinline__ void build_h1(__half* buf, const __half* suS,
                                         const __half* suR, int eb, int tid)
{
    int row  = tid >> 1;
    int h0   = (tid & 1) * 32;
    int nl   = row >> 5;
    int slot = row & 31;
    int i    = eb * 4 + nl;
    int jj   = (slot == 31) ? i : (slot + (slot >= i ? 1 : 0));
    const uint4* ps = (const uint4*)(suS + jj * H1S + h0);
    const uint4* pr = (const uint4*)(suR + i * H1S + h0);
    uint4* dst = (uint4*)(buf + row * H1S + h0);
    #pragma unroll
    for (int u = 0; u < 4; ++u) {
        uint4 av = ps[u], cv = pr[u], o;
        o.x = h2addrelu(av.x, cv.x);
        o.y = h2addrelu(av.y, cv.y);
        o.z = h2addrelu(av.z, cv.z);
        o.w = h2addrelu(av.w, cv.w);
        dst[u] = o;
    }
}

__global__ void __launch_bounds__(256, 4)
mlpdec_fused_kernel(const float* __restrict__ X,
                    const float* __restrict__ G,
                    const float* __restrict__ W1,
                    const float* __restrict__ b1,
                    const float* __restrict__ b2,
                    const float* __restrict__ bo1,
                    const float* __restrict__ bo2,
                    const float* __restrict__ bo3,
                    float* __restrict__ out)
{
    const int bt  = blockIdx.x;
    const int b   = bt >> 8;
    const int t   = bt & 255;
    const int tid = threadIdx.x;
    const int wid  = tid >> 5;
    const int lane = tid & 31;

    float* sx   = sm + SX_OFF;
    float* sagg = sm + SAGG_OFF;
    float* scr  = sm + SCR_OFF;

    __half* suS = (__half*)(scr);
    __half* suR = (__half*)(scr + 1152);
    __half* h1A = (__half*)(scr + 2304);    // 128 x 72 halfs
    __half* h1B = (__half*)(scr + 6912);    // 128 x 72 halfs
    float*  sgA = scr + 11520;              // 128 gates (buffer A)
    float*  sgB = scr + 11648;              // 128 gates (buffer B)

    // ---- load x ----
    if (tid < Nv * Dv) {
        int n = tid >> 2, d = tid & 3;
        sx[tid] = X[(((b * Nv + n) * Tv + t) << 2) + d];
    }
    __syncthreads();

    // warp roles in edge GEMM (C = W2^T @ h1^T)
    const int node = wid >> 1;
    const int mh   = wid & 1;
    const int r_ = lane >> 2;
    const int c_ = (lane & 3) * 2;

    // ================= edge message passing =================
    for (int k = 0; k < Kv; ++k) {
        if (k > 0) __syncthreads();   // k=0 readers of suS/suR/h1 done

        // per-node projections -> fp16 (W1/b1 straight from global, L1-hot)
        {
            const float* W1k = W1 + k * 512;
            const float* b1k = b1 + k * 64;
            for (int idx = tid; idx < Nv * 64; idx += 256) {
                int n = idx >> 6, h = idx & 63;
                float x0 = sx[n * 4 + 0], x1 = sx[n * 4 + 1];
                float x2 = sx[n * 4 + 2], x3 = sx[n * 4 + 3];
                float vs = x0 * __ldg(W1k + h)       + x1 * __ldg(W1k + 64 + h)
                         + x2 * __ldg(W1k + 128 + h) + x3 * __ldg(W1k + 192 + h);
                float vr = __ldg(b1k + h)
                         + x0 * __ldg(W1k + 256 + h) + x1 * __ldg(W1k + 320 + h)
                         + x2 * __ldg(W1k + 384 + h) + x3 * __ldg(W1k + 448 + h);
                suS[n * H1S + h] = __float2half_rn(vs);
                suR[n * H1S + h] = __float2half_rn(vr);
            }
        }

        // A-fragments: 8 coalesced LDG.128 from the prepacked layout
        uint32_t a[2][4][4];
        {
            const uint4* src = (const uint4*)&g_W2f[k][mh][0][0][0];
            #pragma unroll
            for (int c = 0; c < 8; ++c) {
                uint4 v = __ldg(src + c * 32 + lane);
                a[c >> 2][c & 3][0] = v.x;
                a[c >> 2][c & 3][1] = v.y;
                a[c >> 2][c & 3][2] = v.z;
                a[c >> 2][c & 3][3] = v.w;
            }
        }
        float b2a[2], b2b[2];
        #pragma unroll
        for (int mt = 0; mt < 2; ++mt) {
            b2a[mt] = __ldg(b2 + k * 64 + mh * 32 + mt * 16 + r_);
            b2b[mt] = __ldg(b2 + k * 64 + mh * 32 + mt * 16 + r_ + 8);
        }
        __syncthreads();   // suS/suR ready

        // prologue: build block 0 + its gates
        build_h1(h1A, suS, suR, 0, tid);
        if (tid < 128) {
            int slot = tid & 31;
            int i    = tid >> 5;
            sgA[tid] = (slot < 31) ? __ldg(G + (i * 31 + slot) * 2 + k) : 0.0f;
        }

        for (int eb = 0; eb < NEB; ++eb) {
            __syncthreads();   // build(eb)+gates(eb) visible; prev mma drained

            if (eb < NEB - 1) {
                build_h1((eb & 1) ? h1A : h1B, suS, suR, eb + 1, tid);
                float* gnext = (eb & 1) ? sgA : sgB;
                if (tid < 128) {
                    int slot = tid & 31;
                    int i    = (eb + 1) * 4 + (tid >> 5);
                    gnext[tid] = (slot < 31)
                               ? __ldg(G + (i * 31 + slot) * 2 + k) : 0.0f;
                }
            }

            const __half* h1c = (eb & 1) ? h1B : h1A;
            const float*  sg  = (eb & 1) ? sgB : sgA;
            const uint32_t bbase = smem_u32(h1c)
                + ((lane & 7) * H1S + ((lane >> 3) & 1) * 8) * 2;

            float prs[2][2];
            prs[0][0] = prs[0][1] = prs[1][0] = prs[1][1] = 0.0f;

            #pragma unroll
            for (int nt = 0; nt < 4; ++nt) {
                float acc[2][4];
                acc[0][0] = acc[0][1] = acc[0][2] = acc[0][3] = 0.0f;
                acc[1][0] = acc[1][1] = acc[1][2] = acc[1][3] = 0.0f;
                #pragma unroll
                for (int ks = 0; ks < 4; ++ks) {
                    uint32_t b0r, b1r;
                    ldsm_x2(b0r, b1r,
                            bbase + ((node * 32 + nt * 8) * H1S + ks * 16) * 2);
                    mma16816(acc[0], a[0][ks], b0r, b1r);
                    mma16816(acc[1], a[1][ks], b0r, b1r);
                }
                float2 g2 = *(const float2*)(sg + node * 32 + nt * 8 + c_);
                #pragma unroll
                for (int mt = 0; mt < 2; ++mt) {
                    prs[mt][0] += fmaxf(acc[mt][0] + b2a[mt], 0.0f) * g2.x
                                + fmaxf(acc[mt][1] + b2a[mt], 0.0f) * g2.y;
                    prs[mt][1] += fmaxf(acc[mt][2] + b2b[mt], 0.0f) * g2.x
                                + fmaxf(acc[mt][3] + b2b[mt], 0.0f) * g2.y;
                }
            }

            #pragma unroll
            for (int mt = 0; mt < 2; ++mt) {
                prs[mt][0] += __shfl_xor_sync(0xffffffffu, prs[mt][0], 1);
                prs[mt][0] += __shfl_xor_sync(0xffffffffu, prs[mt][0], 2);
                prs[mt][1] += __shfl_xor_sync(0xffffffffu, prs[mt][1], 1);
                prs[mt][1] += __shfl_xor_sync(0xffffffffu, prs[mt][1], 2);
            }

            if ((lane & 3) == 0) {
                int n = eb * 4 + node;
                #pragma unroll
                for (int mt = 0; mt < 2; ++mt) {
                    int o = n * 64 + mh * 32 + mt * 16 + r_;
                    if (k == 0) {
                        sagg[o]     = prs[mt][0];
                        sagg[o + 8] = prs[mt][1];
                    } else {
                        sagg[o]     += prs[mt][0];
                        sagg[o + 8] += prs[mt][1];
                    }
                }
            }
        }
    }
    __syncthreads();   // sagg complete before node phase

    // ====== node MLP (tensor cores, B-fragments direct from global) ======
    __half* augH = (__half*)(scr);            // 32 x 88
    __half* p1H  = (__half*)(scr + 1408);     // 32 x 136
    __half* p2H  = (__half*)(scr + 8192);     // 32 x 136

    const int nmt = wid & 1;                  // m-tile (16 rows)
    const int ng  = wid >> 1;                 // 16-col group within panel

    // build aug fp16 (32 x 80, pad cols 68..79 = 0)
    for (int i = tid; i < 32 * 80; i += 256) {
        int n = i / 80, c = i % 80;
        float v = (c < 4) ? sx[n * 4 + c]
                 : (c < 68 ? sagg[n * 64 + (c - 4)] : 0.0f);
        augH[n * 88 + c] = __float2half_rn(v);
    }
    __syncthreads();

    // ---- layer 1: aug(32x80) @ Wo1(80x128); A-ldsm shared across panels ----
    {
        float acc[2][2][4];    // [panel][nt][4]
        #pragma unroll
        for (int p = 0; p < 2; ++p)
            #pragma unroll
            for (int nt = 0; nt < 2; ++nt)
                acc[p][nt][0] = acc[p][nt][1] = acc[p][nt][2] = acc[p][nt][3] = 0.0f;

        uint32_t aaddr = smem_u32(augH)
            + ((nmt * 16 + (lane & 15)) * 88 + (lane >> 4) * 8) * 2;
        #pragma unroll
        for (int ks = 0; ks < 5; ++ks) {
            uint32_t a[4];
            ldsm_x4(a, aaddr + ks * 32);
            #pragma unroll
            for (int p = 0; p < 2; ++p) {
                uint4 bf = __ldg(&g_Wo1f[p][ks][ng][lane]);
                mma16816(acc[p][0], a, bf.x, bf.y);
                mma16816(acc[p][1], a, bf.z, bf.w);
            }
        }
        int r = nmt * 16 + r_;
        #pragma unroll
        for (int p = 0; p < 2; ++p)
            #pragma unroll
            for (int nt = 0; nt < 2; ++nt) {
                int c  = p * 64 + ng * 16 + nt * 8 + c_;
                float2 bb = __ldg((const float2*)(bo1 + c));
                *(__half2*)(p1H + r * 136 + c) = __floats2half2_rn(
                    fmaxf(acc[p][nt][0] + bb.x, 0.0f),
                    fmaxf(acc[p][nt][1] + bb.y, 0.0f));
                *(__half2*)(p1H + (r + 8) * 136 + c) = __floats2half2_rn(
                    fmaxf(acc[p][nt][2] + bb.x, 0.0f),
                    fmaxf(acc[p][nt][3] + bb.y, 0.0f));
            }
    }
    __syncthreads();

    // ---- layer 2: p1(32x128) @ Wo2(128x128) ----
    {
        float acc[2][2][4];
        #pragma unroll
        for (int p = 0; p < 2; ++p)
            #pragma unroll
            for (int nt = 0; nt < 2; ++nt)
                acc[p][nt][0] = acc[p][nt][1] = acc[p][nt][2] = acc[p][nt][3] = 0.0f;

        uint32_t aaddr = smem_u32(p1H)
            + ((nmt * 16 + (lane & 15)) * 136 + (lane >> 4) * 8) * 2;
        #pragma unroll
        for (int ks = 0; ks < 8; ++ks) {
            uint32_t a[4];
            ldsm_x4(a, aaddr + ks * 32);
            #pragma unroll
            for (int p = 0; p < 2; ++p) {
                uint4 bf = __ldg(&g_Wo2f[p][ks][ng][lane]);
                mma16816(acc[p][0], a, bf.x, bf.y);
                mma16816(acc[p][1], a, bf.z, bf.w);
            }
        }
        int r = nmt * 16 + r_;
        #pragma unroll
        for (int p = 0; p < 2; ++p)
            #pragma unroll
            for (int nt = 0; nt < 2; ++nt) {
                int c  = p * 64 + ng * 16 + nt * 8 + c_;
                float2 bb = __ldg((const float2*)(bo2 + c));
                *(__half2*)(p2H + r * 136 + c) = __floats2half2_rn(
                    fmaxf(acc[p][nt][0] + bb.x, 0.0f),
                    fmaxf(acc[p][nt][1] + bb.y, 0.0f));
                *(__half2*)(p2H + (r + 8) * 136 + c) = __floats2half2_rn(
                    fmaxf(acc[p][nt][2] + bb.x, 0.0f),
                    fmaxf(acc[p][nt][3] + bb.y, 0.0f));
            }
    }
    __syncthreads();

    // ---- layer 3 on tensor cores: p2(32x128) @ Wo3(128x4->8) + residual ----
    if (wid < 2 && t < Tv - 1) {
        float acc[4];
        acc[0] = acc[1] = acc[2] = acc[3] = 0.0f;
        uint32_t aaddr = smem_u32(p2H)
            + ((wid * 16 + (lane & 15)) * 136 + (lane >> 4) * 8) * 2;
        #pragma unroll
        for (int ks = 0; ks < 8; ++ks) {
            uint32_t a[4];
            ldsm_x4(a, aaddr + ks * 32);
            uint2 bf = __ldg(&g_Wo3f[ks][lane]);
            mma16816(acc, a, bf.x, bf.y);
        }
        int d0 = (lane & 3) * 2;
        if (d0 < 4) {
            float2 bb = __ldg((const float2*)(bo3 + d0));
            #pragma unroll
            for (int half = 0; half < 2; ++half) {
                int n = wid * 16 + r_ + half * 8;
                float2 o;
                o.x = acc[half * 2 + 0] + bb.x + sx[n * 4 + d0];
                o.y = acc[half * 2 + 1] + bb.y + sx[n * 4 + d0 + 1];
                *(float2*)(out + (((b * Nv + n) * (Tv - 1) + t) << 2) + d0) = o;
            }
        }
    }
}

extern "C" void kernel_launch(void* const* d_in, const int* in_sizes, int n_in,
                              void* d_out, int out_size)
{
    const float* X   = (const float*)d_in[0];
    const float* G   = (const float*)d_in[3];
    const float* W1  = (const float*)d_in[4];
    const float* b1  = (const float*)d_in[5];
    const float* W2  = (const float*)d_in[6];
    const float* b2  = (const float*)d_in[7];
    const float* Wo1 = (const float*)d_in[8];
    const float* bo1 = (const float*)d_in[9];
    const float* Wo2 = (const float*)d_in[10];
    const float* bo2 = (const float*)d_in[11];
    const float* Wo3 = (const float*)d_in[12];
    const float* bo3 = (const float*)d_in[13];
    float* out = (float*)d_out;

    cudaFuncSetAttribute(mlpdec_fused_kernel,
                         cudaFuncAttributeMaxDynamicSharedMemorySize, SMEM_BYTES);

    // merged weight repack + rel_graph bcast (single launch before main)
    prep_kernel<<<64, 256>>>(W2, Wo1, Wo2, Wo3, G, out);

    mlpdec_fused_kernel<<<Bv * Tv, 256, SMEM_BYTES>>>(
        X, G, W1, b1, b2, bo1, bo2, bo3, out);
}